// round 1
// baseline (speedup 1.0000x reference)
#include <cuda_runtime.h>

// Shapes (fixed by the problem)
#define S_   4
#define B_   8
#define L_   512
#define D_   128
#define H_   128
#define NOP_ 64
#define W_   2048   // S_*L_

// ---------------- scratch (device globals; no allocation) ----------------
__device__ float g_agg[B_ * W_ * 3 * D_];  // per selected word: [a_o | a_k(normed) | a_s(normed)]
__device__ float g_coef[B_ * W_ * 4];      // c_o, flag_k, flag_s
__device__ float g_u[B_ * W_ * D_];        // word_updated for selected words
__device__ int   g_list[B_ * W_];          // compacted selected bw indices
__device__ int   g_n;                      // count

// ---------------- helpers ----------------
__device__ __forceinline__ float4 shfl4(float4 v, int src) {
    float4 r;
    r.x = __shfl_sync(0xffffffffu, v.x, src);
    r.y = __shfl_sync(0xffffffffu, v.y, src);
    r.z = __shfl_sync(0xffffffffu, v.z, src);
    r.w = __shfl_sync(0xffffffffu, v.w, src);
    return r;
}
__device__ __forceinline__ void fma4(float4& a, float s, const float4 w) {
    a.x = fmaf(s, w.x, a.x);
    a.y = fmaf(s, w.y, a.y);
    a.z = fmaf(s, w.z, a.z);
    a.w = fmaf(s, w.w, a.w);
}
__device__ __forceinline__ void add4(float4& a, const float4 v) {
    a.x += v.x; a.y += v.y; a.z += v.z; a.w += v.w;
}

// ---------------- kernel 0: reset compaction counter ----------------
__global__ void k_reset() {
    if (threadIdx.x == 0) g_n = 0;
}

// ---------------- kernel 1: aggregate neighbors in D-space ----------------
// grid (W_, B_), block 128. One block per (word, batch); early exit if word
// does not contribute to the goal pooling.
__global__ void __launch_bounds__(128) k_aggregate(
    const float* __restrict__ word_outputs,     // [S,B,L,D]
    const float* __restrict__ op_embedding,     // [B,NOP,D]
    const float* __restrict__ word_operator,    // [B,W,NOP]
    const float* __restrict__ word_word,        // [B,W,W]
    const float* __restrict__ depend_relation,  // [S,B,L,L]
    const float* __restrict__ word_exist_matrix,// [B,W,W]
    const float* __restrict__ word_exist_seq,   // [B,W]
    const float* __restrict__ goal_word)        // [B,W]
{
    const int w = blockIdx.x, b = blockIdx.y;
    const int bw = b * W_ + w;
    if (goal_word[bw] == 0.f || word_exist_seq[bw] == 0.f) return;

    const int tid = threadIdx.x;
    const int lane = tid & 31, wid = tid >> 5;

    float4 accO = {0.f,0.f,0.f,0.f}, accK = {0.f,0.f,0.f,0.f}, accS = {0.f,0.f,0.f,0.f};
    int cO = 0, cK = 0, cS = 0;

    // ---- operator aggregation (64 cols; warps 0,1) ----
    if (wid < 2) {
        const float* wo = word_operator + (size_t)bw * NOP_;
        int col = wid * 32 + lane;
        unsigned bal = __ballot_sync(0xffffffffu, wo[col] != 0.f);
        cO = __popc(bal);
        while (bal) {
            int j = __ffs(bal) - 1; bal &= bal - 1;
            int n = wid * 32 + j;
            const float4 e = *(const float4*)(op_embedding + ((size_t)(b * NOP_ + n)) * D_ + 4 * lane);
            add4(accO, e);
        }
    }

    // ---- knowledge aggregation over word_word * word_exist_matrix (2048 cols) ----
    {
        const float* ww  = word_word + (size_t)bw * W_;
        const float* wem = word_exist_matrix + (size_t)bw * W_;
        #pragma unroll 4
        for (int c = 0; c < 16; ++c) {
            int col = wid * 512 + c * 32 + lane;
            float m = ww[col] * wem[col];
            unsigned bal = __ballot_sync(0xffffffffu, m != 0.f);
            cK += __popc(bal);
            int cbase = wid * 512 + c * 32;
            while (bal) {
                int j = __ffs(bal) - 1; bal &= bal - 1;
                int w2 = cbase + j;
                int s2 = w2 >> 9, l2 = w2 & 511;
                const float4 v = *(const float4*)(word_outputs +
                    (((size_t)s2 * B_ + b) * L_ + l2) * D_ + 4 * lane);
                add4(accK, v);
            }
        }
    }

    // ---- segment dependency aggregation (512 cols, same segment) ----
    {
        const int s = w >> 9, l = w & 511;
        const float* dep = depend_relation + (((size_t)s * B_ + b) * L_ + l) * L_;
        const float* xb  = word_outputs + ((size_t)s * B_ + b) * L_ * D_;
        #pragma unroll
        for (int c = 0; c < 4; ++c) {
            int col = wid * 128 + c * 32 + lane;
            unsigned bal = __ballot_sync(0xffffffffu, dep[col] != 0.f);
            cS += __popc(bal);
            int cbase = wid * 128 + c * 32;
            while (bal) {
                int j = __ffs(bal) - 1; bal &= bal - 1;
                const float4 v = *(const float4*)(xb + (size_t)(cbase + j) * D_ + 4 * lane);
                add4(accS, v);
            }
        }
    }

    // ---- cross-warp combine ----
    __shared__ float comb[4][3][128];
    __shared__ int   scn[4][3];
    *(float4*)&comb[wid][0][4 * lane] = accO;
    *(float4*)&comb[wid][1][4 * lane] = accK;
    *(float4*)&comb[wid][2][4 * lane] = accS;
    if (lane == 0) { scn[wid][0] = cO; scn[wid][1] = cK; scn[wid][2] = cS; }
    __syncthreads();

    const int d = tid;
    float aO = comb[0][0][d] + comb[1][0][d] + comb[2][0][d] + comb[3][0][d];
    float aK = comb[0][1][d] + comb[1][1][d] + comb[2][1][d] + comb[3][1][d];
    float aS = comb[0][2][d] + comb[1][2][d] + comb[2][2][d] + comb[3][2][d];
    int tK = scn[0][1] + scn[1][1] + scn[2][1] + scn[3][1];
    int tS = scn[0][2] + scn[1][2] + scn[2][2] + scn[3][2];
    float invK = 1.f / ((float)tK + 1e-30f);
    float invS = 1.f / ((float)tS + 1e-30f);

    float* ag = g_agg + (size_t)bw * 384;
    ag[d]       = aO;
    ag[128 + d] = aK * invK;
    ag[256 + d] = aS * invS;
    if (tid == 0) {
        int tO = scn[0][0] + scn[1][0];
        g_coef[bw * 4 + 0] = (float)tO;             // operator bias scale
        g_coef[bw * 4 + 1] = (float)tK * invK;      // row-sum of normalized adj
        g_coef[bw * 4 + 2] = (float)tS * invS;
        int pos = atomicAdd(&g_n, 1);
        g_list[pos] = bw;
    }
}

// ---------------- kernel 2: GEMVs + L2 norms + up-projection ----------------
// Each warp processes 8 compacted words in lockstep so every weight float4
// load is amortized across 8 words. Lane owns output dims [4*lane, 4*lane+4).
__global__ void __launch_bounds__(128) k_update(
    const float* __restrict__ o_w_W, const float* __restrict__ o_w_b,
    const float* __restrict__ wk_W,  const float* __restrict__ wk_b,
    const float* __restrict__ ws_W,  const float* __restrict__ ws_b,
    const float* __restrict__ up_W,  const float* __restrict__ up_b)
{
    const int lane = threadIdx.x & 31, wid = threadIdx.x >> 5;
    const int gwarp = blockIdx.x * 4 + wid;
    const int nwarps = gridDim.x * 4;
    const int N = g_n;

    const float4 bU = ((const float4*)up_b)[lane];
    const float4* upW4 = (const float4*)up_W;
    const float* Wf[3] = { o_w_W, wk_W, ws_W };
    const float* bf[3] = { o_w_b, wk_b, ws_b };

    for (int base = gwarp * 8; base < N; base += nwarps * 8) {
        int idx[8]; bool val[8];
        #pragma unroll
        for (int g = 0; g < 8; ++g) {
            val[g] = (base + g) < N;
            idx[g] = val[g] ? g_list[base + g] : 0;
        }
        float4 u[8];
        #pragma unroll
        for (int g = 0; g < 8; ++g) u[g] = bU;

        #pragma unroll
        for (int part = 0; part < 3; ++part) {
            const float4* W4 = (const float4*)Wf[part];
            const float4 bia = ((const float4*)bf[part])[lane];
            float4 a[8], h[8];
            #pragma unroll
            for (int g = 0; g < 8; ++g) {
                if (val[g]) {
                    a[g] = *(const float4*)(g_agg + (size_t)idx[g] * 384 + part * 128 + 4 * lane);
                    float cf = g_coef[idx[g] * 4 + part];
                    h[g] = make_float4(cf * bia.x, cf * bia.y, cf * bia.z, cf * bia.w);
                } else {
                    a[g] = make_float4(0.f,0.f,0.f,0.f);
                    h[g] = make_float4(0.f,0.f,0.f,0.f);
                }
            }
            // feature GEMV: h = a @ W  (weights broadcast across the 8 words)
            #pragma unroll 4
            for (int src = 0; src < 32; ++src) {
                float4 w0 = W4[(src * 4 + 0) * 32 + lane];
                float4 w1 = W4[(src * 4 + 1) * 32 + lane];
                float4 w2 = W4[(src * 4 + 2) * 32 + lane];
                float4 w3 = W4[(src * 4 + 3) * 32 + lane];
                #pragma unroll
                for (int g = 0; g < 8; ++g) {
                    float4 av = shfl4(a[g], src);
                    fma4(h[g], av.x, w0); fma4(h[g], av.y, w1);
                    fma4(h[g], av.z, w2); fma4(h[g], av.w, w3);
                }
            }
            // L2 normalize each word's 128-vector
            #pragma unroll
            for (int g = 0; g < 8; ++g) {
                float ss = h[g].x*h[g].x + h[g].y*h[g].y + h[g].z*h[g].z + h[g].w*h[g].w;
                ss += __shfl_xor_sync(0xffffffffu, ss, 16);
                ss += __shfl_xor_sync(0xffffffffu, ss, 8);
                ss += __shfl_xor_sync(0xffffffffu, ss, 4);
                ss += __shfl_xor_sync(0xffffffffu, ss, 2);
                ss += __shfl_xor_sync(0xffffffffu, ss, 1);
                float inv = 1.f / (sqrtf(ss) + 1e-30f);
                h[g].x *= inv; h[g].y *= inv; h[g].z *= inv; h[g].w *= inv;
            }
            // up-projection accumulate: u += h_part @ up_W[part*128 : part*128+128, :]
            #pragma unroll 4
            for (int src = 0; src < 32; ++src) {
                const float4* up = upW4 + (size_t)(part * 128 + src * 4) * 32 + lane;
                float4 w0 = up[0], w1 = up[32], w2 = up[64], w3 = up[96];
                #pragma unroll
                for (int g = 0; g < 8; ++g) {
                    float4 nv = shfl4(h[g], src);
                    fma4(u[g], nv.x, w0); fma4(u[g], nv.y, w1);
                    fma4(u[g], nv.z, w2); fma4(u[g], nv.w, w3);
                }
            }
        }
        // relu + scatter
        #pragma unroll
        for (int g = 0; g < 8; ++g) {
            if (val[g]) {
                float4 r;
                r.x = fmaxf(u[g].x, 0.f); r.y = fmaxf(u[g].y, 0.f);
                r.z = fmaxf(u[g].z, 0.f); r.w = fmaxf(u[g].w, 0.f);
                *(float4*)(g_u + (size_t)idx[g] * 128 + 4 * lane) = r;
            }
        }
    }
}

// ---------------- kernel 3: goal pooling + gates + output ----------------
// grid B_, block 128 (thread = output dim d).
__global__ void __launch_bounds__(128) k_final(
    const float* __restrict__ goal_word,
    const float* __restrict__ word_exist_seq,
    const float* __restrict__ node_hidden,  // [B,D]
    const float* __restrict__ wg_W, const float* __restrict__ wg_b,
    const float* __restrict__ fg_W, const float* __restrict__ fg_b,
    float* __restrict__ out)
{
    const int b = blockIdx.x, d = threadIdx.x;
    __shared__ float gws[128], nh[128];

    float acc = 0.f; int cnt = 0;
    const float* gp = goal_word + b * W_;
    const float* ep = word_exist_seq + b * W_;
    const float* ub = g_u + (size_t)b * W_ * 128;
    for (int w = 0; w < W_; ++w) {
        if (gp[w] != 0.f && ep[w] != 0.f) { acc += ub[(size_t)w * 128 + d]; ++cnt; }
    }
    float gw = acc * (1.f / ((float)cnt + 1e-30f));
    gws[d] = gw;
    nh[d] = node_hidden[b * 128 + d];
    __syncthreads();

    float s1 = wg_b[d];
    float s2 = fg_b[d];
    #pragma unroll 4
    for (int k = 0; k < 128; ++k) {
        s1 = fmaf(gws[k], wg_W[k * 128 + d], s1);
        s2 = fmaf(gws[k], fg_W[k * 128 + d], s2);
    }
    #pragma unroll 4
    for (int k = 0; k < 128; ++k)
        s2 = fmaf(nh[k], fg_W[(128 + k) * 128 + d], s2);

    float gu = fmaxf(s1, 0.f);                 // relu(goal_w @ wg_W + wg_b)
    float f  = 1.f / (1.f + expf(-s2));        // sigmoid forget gate
    out[b * 128 + d] = fmaxf(f, 0.1f) * nh[d] + (1.f - f) * gu;
}

// ---------------- launch ----------------
extern "C" void kernel_launch(void* const* d_in, const int* in_sizes, int n_in,
                              void* d_out, int out_size) {
    const float* word_outputs      = (const float*)d_in[0];
    const float* node_hidden       = (const float*)d_in[1];
    const float* op_embedding      = (const float*)d_in[2];
    const float* word_operator     = (const float*)d_in[3];
    const float* word_word         = (const float*)d_in[4];
    const float* depend_relation   = (const float*)d_in[5];
    const float* word_exist_matrix = (const float*)d_in[6];
    const float* word_exist_seq    = (const float*)d_in[7];
    const float* goal_word         = (const float*)d_in[8];
    const float* o_w_W = (const float*)d_in[9];
    const float* o_w_b = (const float*)d_in[10];
    const float* wk_W  = (const float*)d_in[11];
    const float* wk_b  = (const float*)d_in[12];
    const float* ws_W  = (const float*)d_in[13];
    const float* ws_b  = (const float*)d_in[14];
    const float* up_W  = (const float*)d_in[15];
    const float* up_b  = (const float*)d_in[16];
    const float* wg_W  = (const float*)d_in[17];
    const float* wg_b  = (const float*)d_in[18];
    const float* fg_W  = (const float*)d_in[19];
    const float* fg_b  = (const float*)d_in[20];
    float* out = (float*)d_out;

    k_reset<<<1, 32>>>();
    k_aggregate<<<dim3(W_, B_), 128>>>(word_outputs, op_embedding, word_operator,
                                       word_word, depend_relation, word_exist_matrix,
                                       word_exist_seq, goal_word);
    k_update<<<148, 128>>>(o_w_W, o_w_b, wk_W, wk_b, ws_W, ws_b, up_W, up_b);
    k_final<<<B_, 128>>>(goal_word, word_exist_seq, node_hidden,
                         wg_W, wg_b, fg_W, fg_b, out);
}

// round 2
// speedup vs baseline: 2.2333x; 2.2333x over previous
#include <cuda_runtime.h>

// Shapes (fixed by the problem)
#define S_   4
#define B_   8
#define L_   512
#define D_   128
#define H_   128
#define NOP_ 64
#define W_   2048   // S_*L_

// ---------------- scratch (device globals; no allocation) ----------------
__device__ float g_agg[B_ * W_ * 3 * D_];  // per selected word: [a_o | a_k(normed) | a_s(normed)]
__device__ float g_coef[B_ * W_ * 4];      // c_o, rowsumK, rowsumS
__device__ float g_goal[B_ * D_];          // per-batch pooled sum of word_updated
__device__ int   g_bcnt[B_];               // per-batch selected count
__device__ int   g_list[B_ * W_];          // compacted selected bw indices
__device__ int   g_n;                      // count

// ---------------- helpers ----------------
__device__ __forceinline__ float4 shfl4(float4 v, int src) {
    float4 r;
    r.x = __shfl_sync(0xffffffffu, v.x, src);
    r.y = __shfl_sync(0xffffffffu, v.y, src);
    r.z = __shfl_sync(0xffffffffu, v.z, src);
    r.w = __shfl_sync(0xffffffffu, v.w, src);
    return r;
}
__device__ __forceinline__ void fma4(float4& a, float s, const float4 w) {
    a.x = fmaf(s, w.x, a.x);
    a.y = fmaf(s, w.y, a.y);
    a.z = fmaf(s, w.z, a.z);
    a.w = fmaf(s, w.w, a.w);
}
__device__ __forceinline__ void add4(float4& a, const float4 v) {
    a.x += v.x; a.y += v.y; a.z += v.z; a.w += v.w;
}

// ---------------- kernel 0: reset counters + goal accumulators ----------------
__global__ void k_reset() {
    int t = threadIdx.x;
    if (t < B_ * D_) g_goal[t] = 0.f;
    if (t < B_) g_bcnt[t] = 0;
    if (t == 0) g_n = 0;
}

// ---------------- kernel 1: aggregate neighbors in D-space ----------------
// grid (W_, B_), block 128. One block per (word, batch); early exit if word
// does not contribute to the goal pooling.
__global__ void __launch_bounds__(128) k_aggregate(
    const float* __restrict__ word_outputs,     // [S,B,L,D]
    const float* __restrict__ op_embedding,     // [B,NOP,D]
    const float* __restrict__ word_operator,    // [B,W,NOP]
    const float* __restrict__ word_word,        // [B,W,W]
    const float* __restrict__ depend_relation,  // [S,B,L,L]
    const float* __restrict__ word_exist_matrix,// [B,W,W]
    const float* __restrict__ word_exist_seq,   // [B,W]
    const float* __restrict__ goal_word)        // [B,W]
{
    const int w = blockIdx.x, b = blockIdx.y;
    const int bw = b * W_ + w;
    if (goal_word[bw] == 0.f || word_exist_seq[bw] == 0.f) return;

    const int tid = threadIdx.x;
    const int lane = tid & 31, wid = tid >> 5;

    float4 accO = {0.f,0.f,0.f,0.f}, accK = {0.f,0.f,0.f,0.f}, accS = {0.f,0.f,0.f,0.f};
    int cO = 0, cK = 0, cS = 0;

    // ---- operator aggregation (64 cols; warps 0,1) ----
    if (wid < 2) {
        const float* wo = word_operator + (size_t)bw * NOP_;
        int col = wid * 32 + lane;
        unsigned bal = __ballot_sync(0xffffffffu, wo[col] != 0.f);
        cO = __popc(bal);
        while (bal) {
            int j = __ffs(bal) - 1; bal &= bal - 1;
            int n = wid * 32 + j;
            const float4 e = *(const float4*)(op_embedding + ((size_t)(b * NOP_ + n)) * D_ + 4 * lane);
            add4(accO, e);
        }
    }

    // ---- knowledge aggregation over word_word * word_exist_matrix (2048 cols) ----
    {
        const float* ww  = word_word + (size_t)bw * W_;
        const float* wem = word_exist_matrix + (size_t)bw * W_;
        #pragma unroll 4
        for (int c = 0; c < 16; ++c) {
            int col = wid * 512 + c * 32 + lane;
            float m = ww[col] * wem[col];
            unsigned bal = __ballot_sync(0xffffffffu, m != 0.f);
            cK += __popc(bal);
            int cbase = wid * 512 + c * 32;
            while (bal) {
                int j = __ffs(bal) - 1; bal &= bal - 1;
                int w2 = cbase + j;
                int s2 = w2 >> 9, l2 = w2 & 511;
                const float4 v = *(const float4*)(word_outputs +
                    (((size_t)s2 * B_ + b) * L_ + l2) * D_ + 4 * lane);
                add4(accK, v);
            }
        }
    }

    // ---- segment dependency aggregation (512 cols, same segment) ----
    {
        const int s = w >> 9, l = w & 511;
        const float* dep = depend_relation + (((size_t)s * B_ + b) * L_ + l) * L_;
        const float* xb  = word_outputs + ((size_t)s * B_ + b) * L_ * D_;
        #pragma unroll
        for (int c = 0; c < 4; ++c) {
            int col = wid * 128 + c * 32 + lane;
            unsigned bal = __ballot_sync(0xffffffffu, dep[col] != 0.f);
            cS += __popc(bal);
            int cbase = wid * 128 + c * 32;
            while (bal) {
                int j = __ffs(bal) - 1; bal &= bal - 1;
                const float4 v = *(const float4*)(xb + (size_t)(cbase + j) * D_ + 4 * lane);
                add4(accS, v);
            }
        }
    }

    // ---- cross-warp combine ----
    __shared__ float comb[4][3][128];
    __shared__ int   scn[4][3];
    *(float4*)&comb[wid][0][4 * lane] = accO;
    *(float4*)&comb[wid][1][4 * lane] = accK;
    *(float4*)&comb[wid][2][4 * lane] = accS;
    if (lane == 0) { scn[wid][0] = cO; scn[wid][1] = cK; scn[wid][2] = cS; }
    __syncthreads();

    const int d = tid;
    float aO = comb[0][0][d] + comb[1][0][d] + comb[2][0][d] + comb[3][0][d];
    float aK = comb[0][1][d] + comb[1][1][d] + comb[2][1][d] + comb[3][1][d];
    float aS = comb[0][2][d] + comb[1][2][d] + comb[2][2][d] + comb[3][2][d];
    int tK = scn[0][1] + scn[1][1] + scn[2][1] + scn[3][1];
    int tS = scn[0][2] + scn[1][2] + scn[2][2] + scn[3][2];
    float invK = 1.f / ((float)tK + 1e-30f);
    float invS = 1.f / ((float)tS + 1e-30f);

    float* ag = g_agg + (size_t)bw * 384;
    ag[d]       = aO;
    ag[128 + d] = aK * invK;
    ag[256 + d] = aS * invS;
    if (tid == 0) {
        int tO = scn[0][0] + scn[1][0];
        g_coef[bw * 4 + 0] = (float)tO;             // operator bias scale
        g_coef[bw * 4 + 1] = (float)tK * invK;      // row-sum of normalized adj
        g_coef[bw * 4 + 2] = (float)tS * invS;
        int pos = atomicAdd(&g_n, 1);
        g_list[pos] = bw;
        atomicAdd(&g_bcnt[b], 1);
    }
}

// ---------------- kernel 2: GEMVs + L2 norms + up-projection + pooled REDG ----------------
// Each warp processes 8 compacted words in lockstep so every weight float4
// load is amortized across 8 words. Lane owns output dims [4*lane, 4*lane+4).
// The relu'd word_updated row is accumulated straight into the per-batch goal
// pool via atomicAdd (no g_u materialization).
__global__ void __launch_bounds__(128) k_update(
    const float* __restrict__ o_w_W, const float* __restrict__ o_w_b,
    const float* __restrict__ wk_W,  const float* __restrict__ wk_b,
    const float* __restrict__ ws_W,  const float* __restrict__ ws_b,
    const float* __restrict__ up_W,  const float* __restrict__ up_b)
{
    const int lane = threadIdx.x & 31, wid = threadIdx.x >> 5;
    const int gwarp = blockIdx.x * 4 + wid;
    const int nwarps = gridDim.x * 4;
    const int N = g_n;

    const float4 bU = ((const float4*)up_b)[lane];
    const float4* upW4 = (const float4*)up_W;
    const float* Wf[3] = { o_w_W, wk_W, ws_W };
    const float* bf[3] = { o_w_b, wk_b, ws_b };

    for (int base = gwarp * 8; base < N; base += nwarps * 8) {
        int idx[8]; bool val[8];
        #pragma unroll
        for (int g = 0; g < 8; ++g) {
            val[g] = (base + g) < N;
            idx[g] = val[g] ? g_list[base + g] : 0;
        }
        float4 u[8];
        #pragma unroll
        for (int g = 0; g < 8; ++g) u[g] = bU;

        #pragma unroll
        for (int part = 0; part < 3; ++part) {
            const float4* W4 = (const float4*)Wf[part];
            const float4 bia = ((const float4*)bf[part])[lane];
            float4 a[8], h[8];
            #pragma unroll
            for (int g = 0; g < 8; ++g) {
                if (val[g]) {
                    a[g] = *(const float4*)(g_agg + (size_t)idx[g] * 384 + part * 128 + 4 * lane);
                    float cf = g_coef[idx[g] * 4 + part];
                    h[g] = make_float4(cf * bia.x, cf * bia.y, cf * bia.z, cf * bia.w);
                } else {
                    a[g] = make_float4(0.f,0.f,0.f,0.f);
                    h[g] = make_float4(0.f,0.f,0.f,0.f);
                }
            }
            // feature GEMV: h = a @ W  (weights broadcast across the 8 words)
            #pragma unroll 4
            for (int src = 0; src < 32; ++src) {
                float4 w0 = W4[(src * 4 + 0) * 32 + lane];
                float4 w1 = W4[(src * 4 + 1) * 32 + lane];
                float4 w2 = W4[(src * 4 + 2) * 32 + lane];
                float4 w3 = W4[(src * 4 + 3) * 32 + lane];
                #pragma unroll
                for (int g = 0; g < 8; ++g) {
                    float4 av = shfl4(a[g], src);
                    fma4(h[g], av.x, w0); fma4(h[g], av.y, w1);
                    fma4(h[g], av.z, w2); fma4(h[g], av.w, w3);
                }
            }
            // L2 normalize each word's 128-vector
            #pragma unroll
            for (int g = 0; g < 8; ++g) {
                float ss = h[g].x*h[g].x + h[g].y*h[g].y + h[g].z*h[g].z + h[g].w*h[g].w;
                ss += __shfl_xor_sync(0xffffffffu, ss, 16);
                ss += __shfl_xor_sync(0xffffffffu, ss, 8);
                ss += __shfl_xor_sync(0xffffffffu, ss, 4);
                ss += __shfl_xor_sync(0xffffffffu, ss, 2);
                ss += __shfl_xor_sync(0xffffffffu, ss, 1);
                float inv = 1.f / (sqrtf(ss) + 1e-30f);
                h[g].x *= inv; h[g].y *= inv; h[g].z *= inv; h[g].w *= inv;
            }
            // up-projection accumulate: u += h_part @ up_W[part*128 : part*128+128, :]
            #pragma unroll 4
            for (int src = 0; src < 32; ++src) {
                const float4* up = upW4 + (size_t)(part * 128 + src * 4) * 32 + lane;
                float4 w0 = up[0], w1 = up[32], w2 = up[64], w3 = up[96];
                #pragma unroll
                for (int g = 0; g < 8; ++g) {
                    float4 nv = shfl4(h[g], src);
                    fma4(u[g], nv.x, w0); fma4(u[g], nv.y, w1);
                    fma4(u[g], nv.z, w2); fma4(u[g], nv.w, w3);
                }
            }
        }
        // relu + pooled accumulation (REDG float atomics, no return value used)
        #pragma unroll
        for (int g = 0; g < 8; ++g) {
            if (val[g]) {
                int b = idx[g] >> 11;  // W_ = 2048
                float* gp = g_goal + b * D_ + 4 * lane;
                atomicAdd(gp + 0, fmaxf(u[g].x, 0.f));
                atomicAdd(gp + 1, fmaxf(u[g].y, 0.f));
                atomicAdd(gp + 2, fmaxf(u[g].z, 0.f));
                atomicAdd(gp + 3, fmaxf(u[g].w, 0.f));
            }
        }
    }
}

// ---------------- kernel 3: gates + output (tiny, no pooling loop) ----------------
// grid B_, block 128 (thread = output dim d).
__global__ void __launch_bounds__(128) k_final(
    const float* __restrict__ node_hidden,  // [B,D]
    const float* __restrict__ wg_W, const float* __restrict__ wg_b,
    const float* __restrict__ fg_W, const float* __restrict__ fg_b,
    float* __restrict__ out)
{
    const int b = blockIdx.x, d = threadIdx.x;
    __shared__ float gws[128], nh[128];

    float inv = 1.f / ((float)g_bcnt[b] + 1e-30f);
    gws[d] = g_goal[b * D_ + d] * inv;
    nh[d] = node_hidden[b * 128 + d];
    __syncthreads();

    float s1 = wg_b[d];
    float s2 = fg_b[d];
    #pragma unroll 4
    for (int k = 0; k < 128; ++k) {
        s1 = fmaf(gws[k], wg_W[k * 128 + d], s1);
        s2 = fmaf(gws[k], fg_W[k * 128 + d], s2);
    }
    #pragma unroll 4
    for (int k = 0; k < 128; ++k)
        s2 = fmaf(nh[k], fg_W[(128 + k) * 128 + d], s2);

    float gu = fmaxf(s1, 0.f);                 // relu(goal_w @ wg_W + wg_b)
    float f  = 1.f / (1.f + expf(-s2));        // sigmoid forget gate
    out[b * 128 + d] = fmaxf(f, 0.1f) * nh[d] + (1.f - f) * gu;
}

// ---------------- launch ----------------
extern "C" void kernel_launch(void* const* d_in, const int* in_sizes, int n_in,
                              void* d_out, int out_size) {
    const float* word_outputs      = (const float*)d_in[0];
    const float* node_hidden       = (const float*)d_in[1];
    const float* op_embedding      = (const float*)d_in[2];
    const float* word_operator     = (const float*)d_in[3];
    const float* word_word         = (const float*)d_in[4];
    const float* depend_relation   = (const float*)d_in[5];
    const float* word_exist_matrix = (const float*)d_in[6];
    const float* word_exist_seq    = (const float*)d_in[7];
    const float* goal_word         = (const float*)d_in[8];
    const float* o_w_W = (const float*)d_in[9];
    const float* o_w_b = (const float*)d_in[10];
    const float* wk_W  = (const float*)d_in[11];
    const float* wk_b  = (const float*)d_in[12];
    const float* ws_W  = (const float*)d_in[13];
    const float* ws_b  = (const float*)d_in[14];
    const float* up_W  = (const float*)d_in[15];
    const float* up_b  = (const float*)d_in[16];
    const float* wg_W  = (const float*)d_in[17];
    const float* wg_b  = (const float*)d_in[18];
    const float* fg_W  = (const float*)d_in[19];
    const float* fg_b  = (const float*)d_in[20];
    float* out = (float*)d_out;

    k_reset<<<1, 1024>>>();
    k_aggregate<<<dim3(W_, B_), 128>>>(word_outputs, op_embedding, word_operator,
                                       word_word, depend_relation, word_exist_matrix,
                                       word_exist_seq, goal_word);
    k_update<<<148, 128>>>(o_w_W, o_w_b, wk_W, wk_b, ws_W, ws_b, up_W, up_b);
    k_final<<<B_, 128>>>(node_hidden, wg_W, wg_b, fg_W, fg_b, out);
}

// round 4
// speedup vs baseline: 3.4815x; 1.5590x over previous
#include <cuda_runtime.h>

#define S_   4
#define B_   8
#define L_   512
#define D_   128
#define NOP_ 64
#define W_   2048   // S_*L_

// ---------------- scratch (device globals; no allocation) ----------------
__device__ float g_agg[B_ * W_ * 3 * D_];   // per selected word: [h_o | a_k(normed) | a_s(normed)]
__device__ float g_coef[B_ * W_ * 4];       // [unused, rowsumK, rowsumS]
__device__ float g_opproj[B_ * NOP_ * D_];  // op_embedding @ o_w_W + o_w_b
__device__ float g_goal[B_ * D_];           // pooled sum of relu(word_updated)
__device__ int   g_bcnt[B_];
__device__ int   g_list[B_ * W_];
__device__ int   g_n;

// ---------------- helpers ----------------
__device__ __forceinline__ void add4(float4& a, const float4 v) {
    a.x += v.x; a.y += v.y; a.z += v.z; a.w += v.w;
}
__device__ __forceinline__ void team_bar(int tg) {
    asm volatile("bar.sync %0, 64;" :: "r"(tg + 1) : "memory");
}

// ---------------- kernel 1: op projection (+ reset) ----------------
// proj[b,o,:] = op_embedding[b,o,:] @ o_w_W + o_w_b   (bias folded per op row)
// grid (8 opgroups, 8 batches), block 1024.
__global__ void __launch_bounds__(1024) k_opproj(
    const float* __restrict__ op_embedding,
    const float* __restrict__ o_w_W, const float* __restrict__ o_w_b)
{
    const int og = blockIdx.x, b = blockIdx.y;
    const int tid = threadIdx.x;
    const int ol = tid >> 7, h = tid & 127;

    if (og == 0 && b == 0) {           // fold the reset into this kernel
        if (tid < B_ * D_) g_goal[tid] = 0.f;
        if (tid < B_) g_bcnt[tid] = 0;
        if (tid == 0) g_n = 0;
    }

    __shared__ float es[8][128];
    const int o = og * 8 + ol;
    es[ol][h] = op_embedding[((size_t)(b * NOP_ + o)) * D_ + h];
    __syncthreads();

    float acc = o_w_b[h];
    #pragma unroll 8
    for (int dd = 0; dd < 128; ++dd)
        acc = fmaf(es[ol][dd], o_w_W[dd * 128 + h], acc);
    g_opproj[((size_t)(b * NOP_ + o)) * D_ + h] = acc;
}

// ---------------- kernel 2: aggregate neighbors ----------------
// grid (W_, B_), block 128; early exit for non-goal words. Float4 mask reads,
// index lists staged in smem, gathers with MLP-4 accumulators.
__global__ void __launch_bounds__(128) k_aggregate(
    const float* __restrict__ word_outputs,
    const float* __restrict__ word_operator,
    const float* __restrict__ word_word,
    const float* __restrict__ depend_relation,
    const float* __restrict__ word_exist_matrix,
    const float* __restrict__ word_exist_seq,
    const float* __restrict__ goal_word)
{
    const int w = blockIdx.x, b = blockIdx.y;
    const int bw = b * W_ + w;
    if (goal_word[bw] == 0.f || word_exist_seq[bw] == 0.f) return;

    const int tid = threadIdx.x;
    const int lane = tid & 31, wid = tid >> 5;
    const unsigned lt = (1u << lane) - 1u;

    __shared__ int   listK[4][512];
    __shared__ int   listS[4][128];
    __shared__ int   listO[64];
    __shared__ float comb[4][3][128];
    __shared__ int   scn[4][2];

    float4 accO = {0,0,0,0}, accK = {0,0,0,0}, accS = {0,0,0,0};
    int cK = 0, cS = 0;

    // ---- operator part: gather pre-projected rows (H-space), warp 0 only ----
    if (wid == 0) {
        const float4* wo4 = (const float4*)(word_operator + (size_t)bw * NOP_);
        float4 m = (lane < 16) ? wo4[lane] : make_float4(0.f,0.f,0.f,0.f);
        int col0 = lane * 4, cO = 0;
        unsigned bb;
        bb = __ballot_sync(0xffffffffu, m.x != 0.f); if (m.x != 0.f) listO[cO + __popc(bb & lt)] = col0;     cO += __popc(bb);
        bb = __ballot_sync(0xffffffffu, m.y != 0.f); if (m.y != 0.f) listO[cO + __popc(bb & lt)] = col0 + 1; cO += __popc(bb);
        bb = __ballot_sync(0xffffffffu, m.z != 0.f); if (m.z != 0.f) listO[cO + __popc(bb & lt)] = col0 + 2; cO += __popc(bb);
        bb = __ballot_sync(0xffffffffu, m.w != 0.f); if (m.w != 0.f) listO[cO + __popc(bb & lt)] = col0 + 3; cO += __popc(bb);
        __syncwarp();
        const float* pb = g_opproj + (size_t)b * NOP_ * D_;
        float4 o0 = {0,0,0,0}, o1 = {0,0,0,0};
        int i = 0;
        for (; i + 2 <= cO; i += 2) {
            float4 v0 = ((const float4*)(pb + (size_t)listO[i]     * D_))[lane];
            float4 v1 = ((const float4*)(pb + (size_t)listO[i + 1] * D_))[lane];
            add4(o0, v0); add4(o1, v1);
        }
        if (i < cO) add4(o0, ((const float4*)(pb + (size_t)listO[i] * D_))[lane]);
        accO = o0; add4(accO, o1);
    }

    // ---- knowledge part: word_word * word_exist_matrix over 2048 cols ----
    {
        const float4* ww4 = (const float4*)(word_word + (size_t)bw * W_);
        const float4* we4 = (const float4*)(word_exist_matrix + (size_t)bw * W_);
        const int cbase = wid * 512;
        #pragma unroll
        for (int c4 = 0; c4 < 4; ++c4) {
            int vec = wid * 128 + c4 * 32 + lane;
            float4 m1 = ww4[vec], m2 = we4[vec];
            float mx = m1.x * m2.x, my = m1.y * m2.y, mz = m1.z * m2.z, mw = m1.w * m2.w;
            int col0 = cbase + c4 * 128 + lane * 4;
            unsigned bb;
            bb = __ballot_sync(0xffffffffu, mx != 0.f); if (mx != 0.f) listK[wid][cK + __popc(bb & lt)] = col0;     cK += __popc(bb);
            bb = __ballot_sync(0xffffffffu, my != 0.f); if (my != 0.f) listK[wid][cK + __popc(bb & lt)] = col0 + 1; cK += __popc(bb);
            bb = __ballot_sync(0xffffffffu, mz != 0.f); if (mz != 0.f) listK[wid][cK + __popc(bb & lt)] = col0 + 2; cK += __popc(bb);
            bb = __ballot_sync(0xffffffffu, mw != 0.f); if (mw != 0.f) listK[wid][cK + __popc(bb & lt)] = col0 + 3; cK += __popc(bb);
        }
        __syncwarp();
        float4 k0 = {0,0,0,0}, k1 = {0,0,0,0}, k2 = {0,0,0,0}, k3 = {0,0,0,0};
        int i = 0;
        for (; i + 4 <= cK; i += 4) {
            int j0 = listK[wid][i], j1 = listK[wid][i+1], j2 = listK[wid][i+2], j3 = listK[wid][i+3];
            float4 v0 = ((const float4*)(word_outputs + (((size_t)(j0 >> 9) * B_ + b) * L_ + (j0 & 511)) * D_))[lane];
            float4 v1 = ((const float4*)(word_outputs + (((size_t)(j1 >> 9) * B_ + b) * L_ + (j1 & 511)) * D_))[lane];
            float4 v2 = ((const float4*)(word_outputs + (((size_t)(j2 >> 9) * B_ + b) * L_ + (j2 & 511)) * D_))[lane];
            float4 v3 = ((const float4*)(word_outputs + (((size_t)(j3 >> 9) * B_ + b) * L_ + (j3 & 511)) * D_))[lane];
            add4(k0, v0); add4(k1, v1); add4(k2, v2); add4(k3, v3);
        }
        for (; i < cK; ++i) {
            int j0 = listK[wid][i];
            add4(k0, ((const float4*)(word_outputs + (((size_t)(j0 >> 9) * B_ + b) * L_ + (j0 & 511)) * D_))[lane]);
        }
        add4(k0, k1); add4(k2, k3); accK = k0; add4(accK, k2);
    }

    // ---- segment dependency part: 512 cols, same segment ----
    {
        const int s = w >> 9, l = w & 511;
        const float4* dp4 = (const float4*)(depend_relation + (((size_t)s * B_ + b) * L_ + l) * L_);
        const float* xb = word_outputs + ((size_t)s * B_ + b) * L_ * D_;
        float4 m = dp4[wid * 32 + lane];
        int col0 = wid * 128 + lane * 4;
        unsigned bb;
        bb = __ballot_sync(0xffffffffu, m.x != 0.f); if (m.x != 0.f) listS[wid][cS + __popc(bb & lt)] = col0;     cS += __popc(bb);
        bb = __ballot_sync(0xffffffffu, m.y != 0.f); if (m.y != 0.f) listS[wid][cS + __popc(bb & lt)] = col0 + 1; cS += __popc(bb);
        bb = __ballot_sync(0xffffffffu, m.z != 0.f); if (m.z != 0.f) listS[wid][cS + __popc(bb & lt)] = col0 + 2; cS += __popc(bb);
        bb = __ballot_sync(0xffffffffu, m.w != 0.f); if (m.w != 0.f) listS[wid][cS + __popc(bb & lt)] = col0 + 3; cS += __popc(bb);
        __syncwarp();
        float4 s0 = {0,0,0,0}, s1 = {0,0,0,0}, s2 = {0,0,0,0}, s3 = {0,0,0,0};
        int i = 0;
        for (; i + 4 <= cS; i += 4) {
            int j0 = listS[wid][i], j1 = listS[wid][i+1], j2 = listS[wid][i+2], j3 = listS[wid][i+3];
            float4 v0 = ((const float4*)(xb + (size_t)j0 * D_))[lane];
            float4 v1 = ((const float4*)(xb + (size_t)j1 * D_))[lane];
            float4 v2 = ((const float4*)(xb + (size_t)j2 * D_))[lane];
            float4 v3 = ((const float4*)(xb + (size_t)j3 * D_))[lane];
            add4(s0, v0); add4(s1, v1); add4(s2, v2); add4(s3, v3);
        }
        for (; i < cS; ++i)
            add4(s0, ((const float4*)(xb + (size_t)listS[wid][i] * D_))[lane]);
        add4(s0, s1); add4(s2, s3); accS = s0; add4(accS, s2);
    }

    // ---- cross-warp combine ----
    *(float4*)&comb[wid][0][4 * lane] = accO;
    *(float4*)&comb[wid][1][4 * lane] = accK;
    *(float4*)&comb[wid][2][4 * lane] = accS;
    if (lane == 0) { scn[wid][0] = cK; scn[wid][1] = cS; }
    __syncthreads();

    const int d = tid;
    float aO = comb[0][0][d] + comb[1][0][d] + comb[2][0][d] + comb[3][0][d];
    float aK = comb[0][1][d] + comb[1][1][d] + comb[2][1][d] + comb[3][1][d];
    float aS = comb[0][2][d] + comb[1][2][d] + comb[2][2][d] + comb[3][2][d];
    int tK = scn[0][0] + scn[1][0] + scn[2][0] + scn[3][0];
    int tS = scn[0][1] + scn[1][1] + scn[2][1] + scn[3][1];
    float invK = 1.f / ((float)tK + 1e-30f);
    float invS = 1.f / ((float)tS + 1e-30f);

    float* ag = g_agg + (size_t)bw * 384;
    ag[d]       = aO;               // already in H-space, bias included
    ag[128 + d] = aK * invK;
    ag[256 + d] = aS * invS;
    if (tid == 0) {
        g_coef[bw * 4 + 1] = (float)tK * invK;
        g_coef[bw * 4 + 2] = (float)tS * invS;
        int pos = atomicAdd(&g_n, 1);
        g_list[pos] = bw;
        atomicAdd(&g_bcnt[b], 1);
    }
}

// ---------------- kernel 3: GEMVs + norm + up-proj + pooled REDG ----------------
// 2-warp teams; each team does 8 words, each warp 64 of 128 output dims.
// a and normalized h staged in smem (LDS.128 broadcast replaces shfl).
__global__ void __launch_bounds__(256) k_update(
    const float* __restrict__ wk_W, const float* __restrict__ wk_b,
    const float* __restrict__ ws_W, const float* __restrict__ ws_b,
    const float* __restrict__ up_W, const float* __restrict__ up_b)
{
    const int tid = threadIdx.x;
    const int lane = tid & 31, wid = tid >> 5;
    const int half = wid & 1, tg = wid >> 1;
    const int t64 = tid & 63;
    const int team = blockIdx.x * 4 + tg;
    const int nteams = gridDim.x * 4;
    const int N = g_n;
    const int dim0 = half * 64 + lane * 2;

    __shared__ float as[4][8][128];
    __shared__ float hs[4][8][128];
    __shared__ float ssp[4][8][2];

    const float2 bU = *(const float2*)(up_b + dim0);

    for (int base = team * 8; base < N; base += nteams * 8) {
        int idx[8]; bool val[8];
        #pragma unroll
        for (int g = 0; g < 8; ++g) {
            val[g] = (base + g) < N;
            idx[g] = val[g] ? g_list[base + g] : 0;
        }
        float2 u[8];
        #pragma unroll
        for (int g = 0; g < 8; ++g) u[g] = bU;

        #pragma unroll
        for (int p = 0; p < 3; ++p) {
            // stage aggregates for this part
            #pragma unroll
            for (int r = 0; r < 4; ++r) {
                int q = r * 64 + t64;
                int g = q >> 5, off = (q & 31) * 4;
                float4 v = val[g] ? *(const float4*)(g_agg + (size_t)idx[g] * 384 + p * 128 + off)
                                  : make_float4(0.f,0.f,0.f,0.f);
                *(float4*)(&as[tg][g][off]) = v;
            }
            team_bar(tg);

            float2 h[8];
            if (p == 0) {
                #pragma unroll
                for (int g = 0; g < 8; ++g) h[g] = *(const float2*)(&as[tg][g][dim0]);
            } else {
                const float* Wp = (p == 1) ? wk_W : ws_W;
                const float* bp = (p == 1) ? wk_b : ws_b;
                const float2 bia = *(const float2*)(bp + dim0);
                #pragma unroll
                for (int g = 0; g < 8; ++g) {
                    float cf = val[g] ? g_coef[idx[g] * 4 + p] : 0.f;
                    h[g] = make_float2(cf * bia.x, cf * bia.y);
                }
                #pragma unroll 4
                for (int s4 = 0; s4 < 32; ++s4) {
                    float2 w0 = *(const float2*)(Wp + (s4 * 4 + 0) * 128 + dim0);
                    float2 w1 = *(const float2*)(Wp + (s4 * 4 + 1) * 128 + dim0);
                    float2 w2 = *(const float2*)(Wp + (s4 * 4 + 2) * 128 + dim0);
                    float2 w3 = *(const float2*)(Wp + (s4 * 4 + 3) * 128 + dim0);
                    #pragma unroll
                    for (int g = 0; g < 8; ++g) {
                        float4 av = *(const float4*)(&as[tg][g][s4 * 4]);
                        h[g].x = fmaf(av.x, w0.x, fmaf(av.y, w1.x, fmaf(av.z, w2.x, fmaf(av.w, w3.x, h[g].x))));
                        h[g].y = fmaf(av.x, w0.y, fmaf(av.y, w1.y, fmaf(av.z, w2.y, fmaf(av.w, w3.y, h[g].y))));
                    }
                }
            }
            // L2 norm across the team (warp half-reduction + smem exchange)
            #pragma unroll
            for (int g = 0; g < 8; ++g) {
                float ss = h[g].x * h[g].x + h[g].y * h[g].y;
                ss += __shfl_xor_sync(0xffffffffu, ss, 16);
                ss += __shfl_xor_sync(0xffffffffu, ss, 8);
                ss += __shfl_xor_sync(0xffffffffu, ss, 4);
                ss += __shfl_xor_sync(0xffffffffu, ss, 2);
                ss += __shfl_xor_sync(0xffffffffu, ss, 1);
                if (lane == 0) ssp[tg][g][half] = ss;
            }
            team_bar(tg);
            #pragma unroll
            for (int g = 0; g < 8; ++g) {
                float inv = 1.f / (sqrtf(ssp[tg][g][0] + ssp[tg][g][1]) + 1e-30f);
                *(float2*)(&hs[tg][g][dim0]) = make_float2(h[g].x * inv, h[g].y * inv);
            }
            team_bar(tg);
            // up-projection for this part
            const float* Up = up_W + (size_t)p * 128 * 128;
            #pragma unroll 4
            for (int s4 = 0; s4 < 32; ++s4) {
                float2 w0 = *(const float2*)(Up + (s4 * 4 + 0) * 128 + dim0);
                float2 w1 = *(const float2*)(Up + (s4 * 4 + 1) * 128 + dim0);
                float2 w2 = *(const float2*)(Up + (s4 * 4 + 2) * 128 + dim0);
                float2 w3 = *(const float2*)(Up + (s4 * 4 + 3) * 128 + dim0);
                #pragma unroll
                for (int g = 0; g < 8; ++g) {
                    float4 hv = *(const float4*)(&hs[tg][g][s4 * 4]);
                    u[g].x = fmaf(hv.x, w0.x, fmaf(hv.y, w1.x, fmaf(hv.z, w2.x, fmaf(hv.w, w3.x, u[g].x))));
                    u[g].y = fmaf(hv.x, w0.y, fmaf(hv.y, w1.y, fmaf(hv.z, w2.y, fmaf(hv.w, w3.y, u[g].y))));
                }
            }
            team_bar(tg);  // protect as/hs reuse in next part
        }
        // relu + pooled accumulation
        #pragma unroll
        for (int g = 0; g < 8; ++g) {
            if (val[g]) {
                int b = idx[g] >> 11;
                atomicAdd(g_goal + b * 128 + dim0,     fmaxf(u[g].x, 0.f));
                atomicAdd(g_goal + b * 128 + dim0 + 1, fmaxf(u[g].y, 0.f));
            }
        }
    }
}

// ---------------- kernel 4: gates + output ----------------
// grid B_, block 1024: k-split across 8 sub-groups to hide load latency.
__global__ void __launch_bounds__(1024) k_final(
    const float* __restrict__ node_hidden,
    const float* __restrict__ wg_W, const float* __restrict__ wg_b,
    const float* __restrict__ fg_W, const float* __restrict__ fg_b,
    float* __restrict__ out)
{
    const int b = blockIdx.x;
    const int tid = threadIdx.x;
    const int d = tid & 127, kq = tid >> 7;
    __shared__ float gws[128], nh[128];
    __shared__ float p1[8][128], p2[8][128];

    if (tid < 128) {
        float inv = 1.f / ((float)g_bcnt[b] + 1e-30f);
        gws[tid] = g_goal[b * 128 + tid] * inv;
        nh[tid] = node_hidden[b * 128 + tid];
    }
    __syncthreads();

    float s1 = 0.f, s2 = 0.f;
    #pragma unroll
    for (int kk = 0; kk < 16; ++kk) {
        int k = kq * 16 + kk;
        s1 = fmaf(gws[k], wg_W[k * 128 + d], s1);
    }
    #pragma unroll
    for (int kk = 0; kk < 32; ++kk) {
        int k = kq * 32 + kk;
        float x = (k < 128) ? gws[k] : nh[k - 128];
        s2 = fmaf(x, fg_W[k * 128 + d], s2);
    }
    p1[kq][d] = s1; p2[kq][d] = s2;
    __syncthreads();

    if (tid < 128) {
        float t1 = wg_b[tid], t2 = fg_b[tid];
        #pragma unroll
        for (int q = 0; q < 8; ++q) { t1 += p1[q][tid]; t2 += p2[q][tid]; }
        float gu = fmaxf(t1, 0.f);
        float f = 1.f / (1.f + expf(-t2));
        out[b * 128 + tid] = fmaxf(f, 0.1f) * nh[tid] + (1.f - f) * gu;
    }
}

// ---------------- launch ----------------
extern "C" void kernel_launch(void* const* d_in, const int* in_sizes, int n_in,
                              void* d_out, int out_size) {
    const float* word_outputs      = (const float*)d_in[0];
    const float* node_hidden       = (const float*)d_in[1];
    const float* op_embedding      = (const float*)d_in[2];
    const float* word_operator     = (const float*)d_in[3];
    const float* word_word         = (const float*)d_in[4];
    const float* depend_relation   = (const float*)d_in[5];
    const float* word_exist_matrix = (const float*)d_in[6];
    const float* word_exist_seq    = (const float*)d_in[7];
    const float* goal_word         = (const float*)d_in[8];
    const float* o_w_W = (const float*)d_in[9];
    const float* o_w_b = (const float*)d_in[10];
    const float* wk_W  = (const float*)d_in[11];
    const float* wk_b  = (const float*)d_in[12];
    const float* ws_W  = (const float*)d_in[13];
    const float* ws_b  = (const float*)d_in[14];
    const float* up_W  = (const float*)d_in[15];
    const float* up_b  = (const float*)d_in[16];
    const float* wg_W  = (const float*)d_in[17];
    const float* wg_b  = (const float*)d_in[18];
    const float* fg_W  = (const float*)d_in[19];
    const float* fg_b  = (const float*)d_in[20];
    float* out = (float*)d_out;

    k_opproj<<<dim3(8, 8), 1024>>>(op_embedding, o_w_W, o_w_b);
    k_aggregate<<<dim3(W_, B_), 128>>>(word_outputs, word_operator, word_word,
                                       depend_relation, word_exist_matrix,
                                       word_exist_seq, goal_word);
    k_update<<<148, 256>>>(wk_W, wk_b, ws_W, ws_b, up_W, up_b);
    k_final<<<B_, 1024>>>(node_hidden, wg_W, wg_b, fg_W, fg_b, out);
}